// round 1
// baseline (speedup 1.0000x reference)
#include <cuda_runtime.h>
#include <cstdint>

static constexpr int NG      = 2500;
static constexpr int NT      = 20000;
static constexpr int NE      = 640000;
static constexpr int SRC_DIM = 128;
static constexpr int DST_DIM = 500;
static constexpr int HID     = 128;
static constexpr int OUTD    = 128;
static constexpr int NCLS    = 16;

// ---------------- scratch (device globals: no allocation allowed) ----------------
__device__ float g_agg[NT * SRC_DIM];   // mean-aggregated gene feats per train node
__device__ float g_h1[NT * HID];
__device__ float g_h2[NT * OUTD];
__device__ float g_h3[NT * OUTD];
__device__ int   g_deg[NT];
__device__ int   g_rowptr[NT + 1];
__device__ int   g_cursor[NT];
__device__ int   g_colidx[NE];

// ---------------- CSR build ----------------
__global__ void k_init() {
    int i = blockIdx.x * blockDim.x + threadIdx.x;
    if (i < NT) { g_deg[i] = 0; g_cursor[i] = 0; }
}

__global__ void k_hist(const int* __restrict__ dst) {
    int e = blockIdx.x * blockDim.x + threadIdx.x;
    if (e < NE) atomicAdd(&g_deg[dst[e]], 1);
}

// single-block exclusive scan of g_deg -> g_rowptr (20001 entries)
__global__ void k_scan() {
    __shared__ int sm[1024];
    __shared__ int carry;
    int tid = threadIdx.x;
    if (tid == 0) carry = 0;
    __syncthreads();
    for (int base = 0; base < NT; base += 1024) {
        int i = base + tid;
        int v = (i < NT) ? g_deg[i] : 0;
        sm[tid] = v;
        __syncthreads();
        #pragma unroll
        for (int off = 1; off < 1024; off <<= 1) {
            int t = (tid >= off) ? sm[tid - off] : 0;
            __syncthreads();
            sm[tid] += t;
            __syncthreads();
        }
        if (i < NT) g_rowptr[i] = carry + sm[tid] - v;
        __syncthreads();
        if (tid == 0) carry += sm[1023];
        __syncthreads();
    }
    if (tid == 0) g_rowptr[NT] = carry;
}

__global__ void k_scatter(const int* __restrict__ src, const int* __restrict__ dst) {
    int e = blockIdx.x * blockDim.x + threadIdx.x;
    if (e < NE) {
        int d = dst[e];
        int p = atomicAdd(&g_cursor[d], 1);
        g_colidx[g_rowptr[d] + p] = src[e];
    }
}

// ---------------- SpMM mean: one warp per dst row ----------------
// gene_feats (1.28MB) stays L2-resident; fp64 accumulation makes the sum
// insensitive (to fp32 ulp) to the nondeterministic colidx ordering.
__global__ void __launch_bounds__(256) k_spmm(const float* __restrict__ gene) {
    int row  = (blockIdx.x * blockDim.x + threadIdx.x) >> 5;
    int lane = threadIdx.x & 31;
    if (row >= NT) return;
    int beg = g_rowptr[row];
    int end = g_rowptr[row + 1];
    double a0 = 0.0, a1 = 0.0, a2 = 0.0, a3 = 0.0;
    for (int base = beg; base < end; base += 32) {
        int myidx = (base + lane < end) ? g_colidx[base + lane] : 0;
        int cnt = min(32, end - base);
        for (int j = 0; j < cnt; ++j) {
            int s = __shfl_sync(0xffffffffu, myidx, j);
            float4 v = *((const float4*)(gene + (size_t)s * SRC_DIM) + lane);
            a0 += (double)v.x; a1 += (double)v.y; a2 += (double)v.z; a3 += (double)v.w;
        }
    }
    float inv = 1.0f / (float)max(end - beg, 1);
    float4 o;
    o.x = (float)a0 * inv; o.y = (float)a1 * inv;
    o.z = (float)a2 * inv; o.w = (float)a3 * inv;
    *((float4*)(g_agg + (size_t)row * SRC_DIM) + lane) = o;
}

// ---------------- fused dual-source GEMM ----------------
// C[M,128] = act( A1[M,K1] @ B1[K1,128] + A2[M,K2] @ B2[K2,128] + bias )
// BM=64, BN=128, BK=16, 256 threads, 4x8 per-thread tile (split-N halves for
// conflict-free LDS.128 b-fragments).
__global__ void __launch_bounds__(256) gemm_dual(
    const float* __restrict__ A1, int K1, const float* __restrict__ B1,
    const float* __restrict__ A2, int K2, const float* __restrict__ B2,
    const float* __restrict__ bias, float* __restrict__ C, int M, int do_relu)
{
    __shared__ float As[16][64];
    __shared__ float Bs[16][128];

    const int tid  = threadIdx.x;
    const int m0   = blockIdx.x * 64;
    const int la_r = tid >> 2;            // 0..63
    const int la_k = (tid & 3) << 2;      // 0,4,8,12
    const int lb_k = tid >> 5;            // 0..7 (+8 on 2nd iter)
    const int lb_c = (tid & 31) << 2;     // 0..124
    const int ty   = tid >> 4;            // 0..15 -> rows ty*4..+3
    const int tx   = tid & 15;            // cols {tx*4..+3} and {64+tx*4..+3}

    float acc[4][8];
    #pragma unroll
    for (int i = 0; i < 4; ++i)
        #pragma unroll
        for (int j = 0; j < 8; ++j) acc[i][j] = 0.f;

    #pragma unroll 1
    for (int pass = 0; pass < 2; ++pass) {
        const float* A = pass ? A2 : A1;
        const float* B = pass ? B2 : B1;
        const int    K = pass ? K2 : K1;
        if (K == 0) continue;

        for (int k0 = 0; k0 < K; k0 += 16) {
            // load A tile (transposed to As[k][m])
            float4 av = make_float4(0.f, 0.f, 0.f, 0.f);
            int ar = m0 + la_r;
            if (ar < M) {
                int kb = k0 + la_k;
                if (kb + 3 < K) {
                    av = *(const float4*)(A + (size_t)ar * K + kb);
                } else {
                    float t[4] = {0.f, 0.f, 0.f, 0.f};
                    #pragma unroll
                    for (int q = 0; q < 4; ++q)
                        if (kb + q < K) t[q] = A[(size_t)ar * K + kb + q];
                    av = make_float4(t[0], t[1], t[2], t[3]);
                }
            }
            As[la_k + 0][la_r] = av.x;
            As[la_k + 1][la_r] = av.y;
            As[la_k + 2][la_r] = av.z;
            As[la_k + 3][la_r] = av.w;

            // load B tile (row-major [K,128])
            #pragma unroll
            for (int it = 0; it < 2; ++it) {
                int bk = k0 + lb_k + it * 8;
                float4 bv = make_float4(0.f, 0.f, 0.f, 0.f);
                if (bk < K) bv = *(const float4*)(B + (size_t)bk * 128 + lb_c);
                *(float4*)&Bs[lb_k + it * 8][lb_c] = bv;
            }
            __syncthreads();

            #pragma unroll
            for (int kk = 0; kk < 16; ++kk) {
                float a[4], b[8];
                *(float4*)a       = *(const float4*)&As[kk][ty * 4];
                *(float4*)b       = *(const float4*)&Bs[kk][tx * 4];
                *(float4*)(b + 4) = *(const float4*)&Bs[kk][64 + tx * 4];
                #pragma unroll
                for (int i = 0; i < 4; ++i)
                    #pragma unroll
                    for (int j = 0; j < 8; ++j)
                        acc[i][j] += a[i] * b[j];
            }
            __syncthreads();
        }
    }

    // epilogue
    float bs0[4], bs1[4];
    #pragma unroll
    for (int j = 0; j < 4; ++j) {
        bs0[j] = bias[tx * 4 + j];
        bs1[j] = bias[64 + tx * 4 + j];
    }
    #pragma unroll
    for (int i = 0; i < 4; ++i) {
        int r = m0 + ty * 4 + i;
        if (r >= M) continue;
        float4 v0, v1;
        v0.x = acc[i][0] + bs0[0]; v0.y = acc[i][1] + bs0[1];
        v0.z = acc[i][2] + bs0[2]; v0.w = acc[i][3] + bs0[3];
        v1.x = acc[i][4] + bs1[0]; v1.y = acc[i][5] + bs1[1];
        v1.z = acc[i][6] + bs1[2]; v1.w = acc[i][7] + bs1[3];
        if (do_relu) {
            v0.x = fmaxf(v0.x, 0.f); v0.y = fmaxf(v0.y, 0.f);
            v0.z = fmaxf(v0.z, 0.f); v0.w = fmaxf(v0.w, 0.f);
            v1.x = fmaxf(v1.x, 0.f); v1.y = fmaxf(v1.y, 0.f);
            v1.z = fmaxf(v1.z, 0.f); v1.w = fmaxf(v1.w, 0.f);
        }
        *(float4*)(C + (size_t)r * 128 + tx * 4)      = v0;
        *(float4*)(C + (size_t)r * 128 + 64 + tx * 4) = v1;
    }
}

// ---------------- classifier tail: out[NT,16] = h3 @ Wc2 + bc2 ----------------
__global__ void __launch_bounds__(256) k_cls(const float* __restrict__ Wc2,
                                             const float* __restrict__ bc2,
                                             float* __restrict__ outp)
{
    __shared__ float w[HID * NCLS];
    __shared__ float bb[NCLS];
    int tid = threadIdx.x;
    for (int i = tid; i < HID * NCLS; i += 256) w[i] = Wc2[i];
    if (tid < NCLS) bb[tid] = bc2[tid];
    __syncthreads();

    int row = blockIdx.x * 16 + (tid >> 4);
    int col = tid & 15;
    if (row >= NT) return;
    const float* hr = g_h3 + (size_t)row * HID;
    float acc = bb[col];
    #pragma unroll 8
    for (int k = 0; k < HID; ++k)
        acc += hr[k] * w[k * NCLS + col];
    outp[(size_t)row * NCLS + col] = acc;
}

// ---------------- launch ----------------
extern "C" void kernel_launch(void* const* d_in, const int* in_sizes, int n_in,
                              void* d_out, int out_size)
{
    const float* gene  = (const float*)d_in[0];
    const float* train = (const float*)d_in[1];
    const int*   esrc  = (const int*)  d_in[2];
    const int*   edst  = (const int*)  d_in[3];
    const float* W1n   = (const float*)d_in[4];
    const float* W1s   = (const float*)d_in[5];
    const float* b1    = (const float*)d_in[6];
    const float* W2n   = (const float*)d_in[7];
    const float* W2s   = (const float*)d_in[8];
    const float* b2    = (const float*)d_in[9];
    const float* Wc1   = (const float*)d_in[10];
    const float* bc1   = (const float*)d_in[11];
    const float* Wc2   = (const float*)d_in[12];
    const float* bc2   = (const float*)d_in[13];
    float* out = (float*)d_out;

    float *agg, *h1, *h2, *h3;
    cudaGetSymbolAddress((void**)&agg, g_agg);
    cudaGetSymbolAddress((void**)&h1,  g_h1);
    cudaGetSymbolAddress((void**)&h2,  g_h2);
    cudaGetSymbolAddress((void**)&h3,  g_h3);

    k_init<<<(NT + 255) / 256, 256>>>();
    k_hist<<<(NE + 255) / 256, 256>>>(edst);
    k_scan<<<1, 1024>>>();
    k_scatter<<<(NE + 255) / 256, 256>>>(esrc, edst);
    k_spmm<<<(NT * 32 + 255) / 256, 256>>>(gene);

    const int gemm_grid = (NT + 63) / 64;  // 313
    // h1 = relu(train @ W1_self + agg @ W1_neigh + b1)
    gemm_dual<<<gemm_grid, 256>>>(train, DST_DIM, W1s, agg, SRC_DIM, W1n, b1, h1, NT, 1);
    // h2 = relu(h1 @ W2_self + agg @ W2_neigh + b2)
    gemm_dual<<<gemm_grid, 256>>>(h1, HID, W2s, agg, SRC_DIM, W2n, b2, h2, NT, 1);
    // h3 = relu(h2 @ Wc1 + bc1)
    gemm_dual<<<gemm_grid, 256>>>(h2, OUTD, Wc1, (const float*)nullptr, 0,
                                  (const float*)nullptr, bc1, h3, NT, 1);
    // out = h3 @ Wc2 + bc2
    k_cls<<<(NT + 15) / 16, 256>>>(Wc2, bc2, out);

    (void)in_sizes; (void)n_in; (void)out_size;
}

// round 2
// speedup vs baseline: 1.2061x; 1.2061x over previous
#include <cuda_runtime.h>
#include <cstdint>

static constexpr int NG      = 2500;
static constexpr int NT      = 20000;
static constexpr int NE      = 640000;
static constexpr int SRC_DIM = 128;
static constexpr int DST_DIM = 500;
static constexpr int HID     = 128;
static constexpr int OUTD    = 128;
static constexpr int NCLS    = 16;

// ---------------- scratch (device globals: no allocation allowed) ----------------
__device__ float g_agg[NT * SRC_DIM];
__device__ float g_h1[NT * HID];
__device__ float g_h2[NT * OUTD];
__device__ float g_h3[NT * OUTD];
__device__ int   g_deg[NT];
__device__ int   g_rowptr[NT + 1];
__device__ int   g_cursor[NT];
__device__ int   g_colidx[NE];

// ---------------- CSR build ----------------
__global__ void k_init() {
    int i = blockIdx.x * blockDim.x + threadIdx.x;
    if (i < NT) g_deg[i] = 0;
}

__global__ void k_hist(const int* __restrict__ dst) {
    int e = blockIdx.x * blockDim.x + threadIdx.x;
    if (e < NE) atomicAdd(&g_deg[dst[e]], 1);
}

// single-block exclusive scan of g_deg -> g_rowptr (20001 entries)
__global__ void k_scan() {
    __shared__ int sm[1024];
    __shared__ int carry;
    int tid = threadIdx.x;
    if (tid == 0) carry = 0;
    __syncthreads();
    for (int base = 0; base < NT; base += 1024) {
        int i = base + tid;
        int v = (i < NT) ? g_deg[i] : 0;
        sm[tid] = v;
        __syncthreads();
        #pragma unroll
        for (int off = 1; off < 1024; off <<= 1) {
            int t = (tid >= off) ? sm[tid - off] : 0;
            __syncthreads();
            sm[tid] += t;
            __syncthreads();
        }
        if (i < NT) g_rowptr[i] = carry + sm[tid] - v;
        __syncthreads();
        if (tid == 0) carry += sm[1023];
        __syncthreads();
    }
    if (tid == 0) g_rowptr[NT] = carry;
}

__global__ void k_cpcur() {
    int i = blockIdx.x * blockDim.x + threadIdx.x;
    if (i < NT) g_cursor[i] = g_rowptr[i];
}

__global__ void k_scatter(const int* __restrict__ src, const int* __restrict__ dst) {
    int e = blockIdx.x * blockDim.x + threadIdx.x;
    if (e < NE) {
        int p = atomicAdd(&g_cursor[dst[e]], 1);
        g_colidx[p] = src[e];
    }
}

// ---------------- SpMM mean: one warp per dst row, fp32, MLP-4 gather ----------------
__global__ void __launch_bounds__(256) k_spmm(const float* __restrict__ gene) {
    int row  = (blockIdx.x * blockDim.x + threadIdx.x) >> 5;
    int lane = threadIdx.x & 31;
    if (row >= NT) return;
    int beg = g_rowptr[row];
    int end = g_rowptr[row + 1];
    float4 a = make_float4(0.f, 0.f, 0.f, 0.f);
    for (int base = beg; base < end; base += 32) {
        int myidx = (base + lane < end) ? g_colidx[base + lane] : 0;
        int cnt = min(32, end - base);
        int j = 0;
        for (; j + 4 <= cnt; j += 4) {
            int s0 = __shfl_sync(0xffffffffu, myidx, j);
            int s1 = __shfl_sync(0xffffffffu, myidx, j + 1);
            int s2 = __shfl_sync(0xffffffffu, myidx, j + 2);
            int s3 = __shfl_sync(0xffffffffu, myidx, j + 3);
            float4 v0 = *((const float4*)(gene + (size_t)s0 * SRC_DIM) + lane);
            float4 v1 = *((const float4*)(gene + (size_t)s1 * SRC_DIM) + lane);
            float4 v2 = *((const float4*)(gene + (size_t)s2 * SRC_DIM) + lane);
            float4 v3 = *((const float4*)(gene + (size_t)s3 * SRC_DIM) + lane);
            a.x += v0.x + v1.x + v2.x + v3.x;
            a.y += v0.y + v1.y + v2.y + v3.y;
            a.z += v0.z + v1.z + v2.z + v3.z;
            a.w += v0.w + v1.w + v2.w + v3.w;
        }
        for (; j < cnt; ++j) {
            int s = __shfl_sync(0xffffffffu, myidx, j);
            float4 v = *((const float4*)(gene + (size_t)s * SRC_DIM) + lane);
            a.x += v.x; a.y += v.y; a.z += v.z; a.w += v.w;
        }
    }
    float inv = 1.0f / (float)max(end - beg, 1);
    a.x *= inv; a.y *= inv; a.z *= inv; a.w *= inv;
    *((float4*)(g_agg + (size_t)row * SRC_DIM) + lane) = a;
}

// ---------------- fused dual-source GEMM, f32x2 inner loop ----------------
// C[M,128] = act( A1[M,K1]@B1[K1,128] + A2[M,K2]@B2[K2,128] + bias )
// BM=64, BN=128, BK=16, 256 threads, 4x8 thread tile, duplicated-A smem for
// packed fma.rn.f32x2 operands, 2-stage double buffering.
__global__ void __launch_bounds__(256) gemm_dual(
    const float* __restrict__ A1, int K1, const float* __restrict__ B1,
    const float* __restrict__ A2, int K2, const float* __restrict__ B2,
    const float* __restrict__ bias, float* __restrict__ C, int M, int do_relu)
{
    __shared__ float As[2][16][128];  // As[s][k][2*m]=As[s][k][2*m+1]=A[m][k]
    __shared__ float Bs[2][16][128];

    const int tid = threadIdx.x;
    const int m0  = blockIdx.x * 64;
    const int T1  = (K1 + 15) >> 4;
    const int T2  = (K2 + 15) >> 4;
    const int T   = T1 + T2;

    const int a_r = tid >> 2;           // 0..63
    const int a_k = (tid & 3) << 2;     // 0,4,8,12
    const int b_k = tid >> 5;           // 0..7 (+8)
    const int b_c = (tid & 31) << 2;    // 0..124
    const int ty  = tid >> 4;           // 0..15 -> rows ty*4..+3
    const int tx  = tid & 15;           // cols tx*4..+3 and 64+tx*4..+3

    float4 areg, breg0, breg1;

    auto fetch = [&](int t) {
        const float* A; const float* B; int K, k0;
        if (t < T1) { A = A1; B = B1; K = K1; k0 = t << 4; }
        else        { A = A2; B = B2; K = K2; k0 = (t - T1) << 4; }
        areg = make_float4(0.f, 0.f, 0.f, 0.f);
        int r = m0 + a_r;
        if (r < M) {
            int kb = k0 + a_k;
            if (kb + 3 < K) {
                areg = *(const float4*)(A + (size_t)r * K + kb);
            } else {
                float tv[4] = {0.f, 0.f, 0.f, 0.f};
                #pragma unroll
                for (int q = 0; q < 4; ++q)
                    if (kb + q < K) tv[q] = A[(size_t)r * K + kb + q];
                areg = make_float4(tv[0], tv[1], tv[2], tv[3]);
            }
        }
        int kb0 = k0 + b_k, kb1 = k0 + b_k + 8;
        breg0 = (kb0 < K) ? *(const float4*)(B + (size_t)kb0 * 128 + b_c)
                          : make_float4(0.f, 0.f, 0.f, 0.f);
        breg1 = (kb1 < K) ? *(const float4*)(B + (size_t)kb1 * 128 + b_c)
                          : make_float4(0.f, 0.f, 0.f, 0.f);
    };
    auto stor = [&](int s) {
        #pragma unroll
        for (int q = 0; q < 4; ++q) {
            float v = (&areg.x)[q];
            *(float2*)&As[s][a_k + q][2 * a_r] = make_float2(v, v);
        }
        *(float4*)&Bs[s][b_k][b_c]     = breg0;
        *(float4*)&Bs[s][b_k + 8][b_c] = breg1;
    };

    unsigned long long acc[4][4];
    #pragma unroll
    for (int i = 0; i < 4; ++i)
        #pragma unroll
        for (int j = 0; j < 4; ++j) acc[i][j] = 0ull;

    fetch(0);
    stor(0);
    __syncthreads();

    for (int t = 0; t < T; ++t) {
        if (t + 1 < T) fetch(t + 1);
        const int s = t & 1;
        #pragma unroll
        for (int kk = 0; kk < 16; ++kk) {
            float4 a01 = *(const float4*)&As[s][kk][8 * ty];      // (a0,a0,a1,a1)
            float4 a23 = *(const float4*)&As[s][kk][8 * ty + 4];  // (a2,a2,a3,a3)
            float4 b0  = *(const float4*)&Bs[s][kk][4 * tx];
            float4 b1  = *(const float4*)&Bs[s][kk][64 + 4 * tx];
            const unsigned long long* pa01 = (const unsigned long long*)&a01;
            const unsigned long long* pa23 = (const unsigned long long*)&a23;
            const unsigned long long* pb0  = (const unsigned long long*)&b0;
            const unsigned long long* pb1  = (const unsigned long long*)&b1;
            unsigned long long ap[4] = {pa01[0], pa01[1], pa23[0], pa23[1]};
            unsigned long long bp[4] = {pb0[0], pb0[1], pb1[0], pb1[1]};
            #pragma unroll
            for (int i = 0; i < 4; ++i)
                #pragma unroll
                for (int j = 0; j < 4; ++j)
                    asm("fma.rn.f32x2 %0, %1, %2, %0;"
                        : "+l"(acc[i][j]) : "l"(ap[i]), "l"(bp[j]));
        }
        if (t + 1 < T) {
            stor((t + 1) & 1);
            __syncthreads();
        }
    }

    // epilogue
    float bs0[4], bs1[4];
    #pragma unroll
    for (int j = 0; j < 4; ++j) {
        bs0[j] = bias[tx * 4 + j];
        bs1[j] = bias[64 + tx * 4 + j];
    }
    #pragma unroll
    for (int i = 0; i < 4; ++i) {
        int r = m0 + ty * 4 + i;
        if (r >= M) continue;
        float2 p0 = *(float2*)&acc[i][0];
        float2 p1 = *(float2*)&acc[i][1];
        float2 p2 = *(float2*)&acc[i][2];
        float2 p3 = *(float2*)&acc[i][3];
        float4 v0 = make_float4(p0.x + bs0[0], p0.y + bs0[1], p1.x + bs0[2], p1.y + bs0[3]);
        float4 v1 = make_float4(p2.x + bs1[0], p2.y + bs1[1], p3.x + bs1[2], p3.y + bs1[3]);
        if (do_relu) {
            v0.x = fmaxf(v0.x, 0.f); v0.y = fmaxf(v0.y, 0.f);
            v0.z = fmaxf(v0.z, 0.f); v0.w = fmaxf(v0.w, 0.f);
            v1.x = fmaxf(v1.x, 0.f); v1.y = fmaxf(v1.y, 0.f);
            v1.z = fmaxf(v1.z, 0.f); v1.w = fmaxf(v1.w, 0.f);
        }
        *(float4*)(C + (size_t)r * 128 + tx * 4)      = v0;
        *(float4*)(C + (size_t)r * 128 + 64 + tx * 4) = v1;
    }
}

// ---------------- classifier tail: out[NT,16] = h3 @ Wc2 + bc2 ----------------
__global__ void __launch_bounds__(256) k_cls(const float* __restrict__ Wc2,
                                             const float* __restrict__ bc2,
                                             float* __restrict__ outp)
{
    __shared__ float w[HID * NCLS];
    __shared__ float bb[NCLS];
    int tid = threadIdx.x;
    for (int i = tid; i < HID * NCLS; i += 256) w[i] = Wc2[i];
    if (tid < NCLS) bb[tid] = bc2[tid];
    __syncthreads();

    int row = blockIdx.x * 16 + (tid >> 4);
    int col = tid & 15;
    if (row >= NT) return;
    const float* hr = g_h3 + (size_t)row * HID;
    float acc = bb[col];
    #pragma unroll 8
    for (int k = 0; k < HID; ++k)
        acc += hr[k] * w[k * NCLS + col];
    outp[(size_t)row * NCLS + col] = acc;
}

// ---------------- launch ----------------
extern "C" void kernel_launch(void* const* d_in, const int* in_sizes, int n_in,
                              void* d_out, int out_size)
{
    const float* gene  = (const float*)d_in[0];
    const float* train = (const float*)d_in[1];
    const int*   esrc  = (const int*)  d_in[2];
    const int*   edst  = (const int*)  d_in[3];
    const float* W1n   = (const float*)d_in[4];
    const float* W1s   = (const float*)d_in[5];
    const float* b1    = (const float*)d_in[6];
    const float* W2n   = (const float*)d_in[7];
    const float* W2s   = (const float*)d_in[8];
    const float* b2    = (const float*)d_in[9];
    const float* Wc1   = (const float*)d_in[10];
    const float* bc1   = (const float*)d_in[11];
    const float* Wc2   = (const float*)d_in[12];
    const float* bc2   = (const float*)d_in[13];
    float* out = (float*)d_out;

    float *agg, *h1, *h2, *h3;
    cudaGetSymbolAddress((void**)&agg, g_agg);
    cudaGetSymbolAddress((void**)&h1,  g_h1);
    cudaGetSymbolAddress((void**)&h2,  g_h2);
    cudaGetSymbolAddress((void**)&h3,  g_h3);

    k_init<<<(NT + 255) / 256, 256>>>();
    k_hist<<<(NE + 255) / 256, 256>>>(edst);
    k_scan<<<1, 1024>>>();
    k_cpcur<<<(NT + 255) / 256, 256>>>();
    k_scatter<<<(NE + 255) / 256, 256>>>(esrc, edst);
    k_spmm<<<(NT * 32 + 255) / 256, 256>>>(gene);

    const int gemm_grid = (NT + 63) / 64;  // 313
    gemm_dual<<<gemm_grid, 256>>>(train, DST_DIM, W1s, agg, SRC_DIM, W1n, b1, h1, NT, 1);
    gemm_dual<<<gemm_grid, 256>>>(h1, HID, W2s, agg, SRC_DIM, W2n, b2, h2, NT, 1);
    gemm_dual<<<gemm_grid, 256>>>(h2, OUTD, Wc1, (const float*)nullptr, 0,
                                  (const float*)nullptr, bc1, h3, NT, 1);
    k_cls<<<(NT + 15) / 16, 256>>>(Wc2, bc2, out);

    (void)in_sizes; (void)n_in; (void)out_size;
}

// round 4
// speedup vs baseline: 2.7233x; 2.2580x over previous
#include <cuda_runtime.h>
#include <cuda_bf16.h>
#include <cstdint>

static constexpr int NG      = 2500;
static constexpr int NT      = 20000;
static constexpr int NE      = 640000;
static constexpr int SRC_DIM = 128;
static constexpr int DST_DIM = 500;
static constexpr int HID     = 128;
static constexpr int OUTD    = 128;
static constexpr int NCLS    = 16;

// ---------------- scratch (device globals: no allocation allowed) ----------------
__device__ float g_agg[NT * SRC_DIM];
__device__ float g_h1[NT * HID];
__device__ float g_h2[NT * OUTD];
__device__ float g_h3[NT * OUTD];
__device__ int   g_deg[NT];
__device__ int   g_rowptr[NT + 1];
__device__ int   g_cursor[NT];
__device__ int   g_colidx[NE];
// weights as bf16 hi/lo planes: [w][plane][n(128)][k(512 padded)]
__device__ __nv_bfloat16 g_wtb[5 * 2 * 128 * 512];

// ---------------- CSR build ----------------
__global__ void k_init() {
    int i = blockIdx.x * blockDim.x + threadIdx.x;
    if (i < NT) g_deg[i] = 0;
}
__global__ void k_hist(const int* __restrict__ dst) {
    int e = blockIdx.x * blockDim.x + threadIdx.x;
    if (e < NE) atomicAdd(&g_deg[dst[e]], 1);
}
__global__ void k_scan() {
    __shared__ int sm[1024];
    __shared__ int carry;
    int tid = threadIdx.x;
    if (tid == 0) carry = 0;
    __syncthreads();
    for (int base = 0; base < NT; base += 1024) {
        int i = base + tid;
        int v = (i < NT) ? g_deg[i] : 0;
        sm[tid] = v;
        __syncthreads();
        #pragma unroll
        for (int off = 1; off < 1024; off <<= 1) {
            int t = (tid >= off) ? sm[tid - off] : 0;
            __syncthreads();
            sm[tid] += t;
            __syncthreads();
        }
        if (i < NT) { int rp = carry + sm[tid] - v; g_rowptr[i] = rp; g_cursor[i] = rp; }
        __syncthreads();
        if (tid == 0) carry += sm[1023];
        __syncthreads();
    }
    if (tid == 0) g_rowptr[NT] = carry;
}
__global__ void k_scatter(const int* __restrict__ src, const int* __restrict__ dst) {
    int e = blockIdx.x * blockDim.x + threadIdx.x;
    if (e < NE) {
        int p = atomicAdd(&g_cursor[dst[e]], 1);
        g_colidx[p] = src[e];
    }
}

// ---------------- SpMM mean: one warp per dst row ----------------
__global__ void __launch_bounds__(256) k_spmm(const float* __restrict__ gene) {
    int row  = (blockIdx.x * blockDim.x + threadIdx.x) >> 5;
    int lane = threadIdx.x & 31;
    if (row >= NT) return;
    int beg = g_rowptr[row];
    int end = g_rowptr[row + 1];
    float4 a = make_float4(0.f, 0.f, 0.f, 0.f);
    for (int base = beg; base < end; base += 32) {
        int myidx = (base + lane < end) ? g_colidx[base + lane] : 0;
        int cnt = min(32, end - base);
        int j = 0;
        for (; j + 4 <= cnt; j += 4) {
            int s0 = __shfl_sync(0xffffffffu, myidx, j);
            int s1 = __shfl_sync(0xffffffffu, myidx, j + 1);
            int s2 = __shfl_sync(0xffffffffu, myidx, j + 2);
            int s3 = __shfl_sync(0xffffffffu, myidx, j + 3);
            float4 v0 = *((const float4*)(gene + (size_t)s0 * SRC_DIM) + lane);
            float4 v1 = *((const float4*)(gene + (size_t)s1 * SRC_DIM) + lane);
            float4 v2 = *((const float4*)(gene + (size_t)s2 * SRC_DIM) + lane);
            float4 v3 = *((const float4*)(gene + (size_t)s3 * SRC_DIM) + lane);
            a.x += v0.x + v1.x + v2.x + v3.x;
            a.y += v0.y + v1.y + v2.y + v3.y;
            a.z += v0.z + v1.z + v2.z + v3.z;
            a.w += v0.w + v1.w + v2.w + v3.w;
        }
        for (; j < cnt; ++j) {
            int s = __shfl_sync(0xffffffffu, myidx, j);
            float4 v = *((const float4*)(gene + (size_t)s * SRC_DIM) + lane);
            a.x += v.x; a.y += v.y; a.z += v.z; a.w += v.w;
        }
    }
    float inv = 1.0f / (float)max(end - beg, 1);
    a.x *= inv; a.y *= inv; a.z *= inv; a.w *= inv;
    *((float4*)(g_agg + (size_t)row * SRC_DIM) + lane) = a;
}

// ---------------- weight transpose + bf16 hi/lo split ----------------
// g_wtb[w][0][n][k] = bf16_hi(W[k][n]); g_wtb[w][1][n][k] = bf16_lo; K padded to 512.
__global__ void k_tr(const float* __restrict__ W1s, const float* __restrict__ W1n,
                     const float* __restrict__ W2s, const float* __restrict__ W2n,
                     const float* __restrict__ Wc1) {
    int idx = blockIdx.x * blockDim.x + threadIdx.x;
    if (idx >= 5 * 128 * 512) return;
    int w   = idx >> 16;
    int rem = idx & 65535;
    int n   = rem >> 9;
    int k   = rem & 511;
    const float* W = (w == 0) ? W1s : (w == 1) ? W1n : (w == 2) ? W2s : (w == 3) ? W2n : Wc1;
    int K = (w == 0) ? DST_DIM : 128;
    float v = (k < K) ? W[(size_t)k * 128 + n] : 0.f;
    __nv_bfloat16 hb = __float2bfloat16_rn(v);
    float lo = v - __bfloat162float(hb);
    g_wtb[(size_t)w * 2 * 128 * 512 + (size_t)n * 512 + k] = hb;
    g_wtb[(size_t)w * 2 * 128 * 512 + 128 * 512 + (size_t)n * 512 + k] = __float2bfloat16_rn(lo);
}

// ---------------- mma.sync bf16 GEMM (3-term split), dual-source fused ----------------
// C[M,128] = act(A1[M,K1]@B1t^T + A2[M,128]@B2t^T + bias)
// CTA 128x128, 4 warps (64x64 each), BK=32 fp32 (=3x32 bf16 effective K).
static constexpr int SP      = 40;                 // bf16 smem pitch (80B, conflict-free)
static constexpr int APITCH  = 36;                 // fp32 staging pitch (144B)
static constexpr int PLANE_B = 128 * SP * 2;       // 10240 bytes per plane-stage tile
static constexpr int OFF_AS  = 0;                  // 4 tiles: [stage][plane]
static constexpr int OFF_BS  = 4 * PLANE_B;        // 40960
static constexpr int OFF_AFP = 8 * PLANE_B;        // 81920
static constexpr int SMEM_GEMM = OFF_AFP + 128 * APITCH * 4;   // 100352

__device__ __forceinline__ uint32_t smem_u32(const void* p) {
    uint32_t a;
    asm("{ .reg .u64 t; cvta.to.shared.u64 t, %1; cvt.u32.u64 %0, t; }" : "=r"(a) : "l"(p));
    return a;
}
#define CP16(dst, src) \
    asm volatile("cp.async.ca.shared.global [%0], [%1], 16;" :: "r"(dst), "l"(src))
#define CP16Z(dst, src, nb) \
    asm volatile("cp.async.ca.shared.global [%0], [%1], 16, %2;" :: "r"(dst), "l"(src), "r"(nb))
#define CP_COMMIT() asm volatile("cp.async.commit_group;" ::: "memory")
#define CP_WAIT1()  asm volatile("cp.async.wait_group 1;" ::: "memory")
#define CP_WAIT0()  asm volatile("cp.async.wait_group 0;" ::: "memory")

__device__ __forceinline__ void mma16816(float* c, const uint32_t* a, const uint32_t* b) {
    asm volatile(
        "mma.sync.aligned.m16n8k16.row.col.f32.bf16.bf16.f32 "
        "{%0,%1,%2,%3}, {%4,%5,%6,%7}, {%8,%9}, {%0,%1,%2,%3};"
        : "+f"(c[0]), "+f"(c[1]), "+f"(c[2]), "+f"(c[3])
        : "r"(a[0]), "r"(a[1]), "r"(a[2]), "r"(a[3]), "r"(b[0]), "r"(b[1]));
}

__global__ void __launch_bounds__(128, 2) gemm_mma(
    const float* __restrict__ A1, int K1, int nch1, const __nv_bfloat16* __restrict__ B1,
    const float* __restrict__ A2, int nch2, const __nv_bfloat16* __restrict__ B2,
    const float* __restrict__ bias, float* __restrict__ C, int Mtot, int relu)
{
    extern __shared__ __align__(16) char smem[];
    const int tid    = threadIdx.x;
    const int lane   = tid & 31;
    const int wid    = tid >> 5;
    const int warp_m = wid >> 1;     // 0..1 -> 64-row band
    const int warp_n = wid & 1;      // 0..1 -> 64-col band
    const int m0     = blockIdx.x * 128;
    const int T      = nch1 + nch2;

    const uint32_t afp_u = smem_u32(smem + OFF_AFP);
    const uint32_t bs_u  = smem_u32(smem + OFF_BS);
    float* Afp = (float*)(smem + OFF_AFP);

    float c[4][8][4];
    #pragma unroll
    for (int i = 0; i < 4; ++i)
        #pragma unroll
        for (int j = 0; j < 8; ++j)
            #pragma unroll
            for (int q = 0; q < 4; ++q) c[i][j][q] = 0.f;

    // ---- cp.async issue of chunk cj into given stage ----
    auto issue = [&](int cj, int stage) {
        const float* A; const __nv_bfloat16* Bw; int K, k0;
        if (cj < nch1) { A = A1; Bw = B1; K = K1; k0 = cj << 5; }
        else           { A = A2; Bw = B2; K = 128; k0 = (cj - nch1) << 5; }
        // A fp32 -> staging (group 1)
        #pragma unroll
        for (int i = 0; i < 8; ++i) {
            int idx = i * 128 + tid;
            int row = idx >> 3, cc = idx & 7;
            int gr = m0 + row, k = k0 + cc * 4;
            int nb = 0;
            if (gr < Mtot) { int rem = K - k; nb = (rem >= 4) ? 16 : (rem > 0 ? rem * 4 : 0); }
            const float* src = nb ? (A + (size_t)gr * K + k) : A;
            CP16Z(afp_u + row * 144 + cc * 16, src, nb);
        }
        CP_COMMIT();
        // B bf16 hi/lo -> Bs[stage] (group 2)
        #pragma unroll
        for (int p = 0; p < 2; ++p) {
            const __nv_bfloat16* bp = Bw + (size_t)p * 128 * 512;
            uint32_t bd = bs_u + (stage * 2 + p) * PLANE_B;
            #pragma unroll
            for (int i = 0; i < 4; ++i) {
                int idx = i * 128 + tid;
                int n = idx >> 2, cc = idx & 3;
                CP16(bd + n * 80 + cc * 16, bp + (size_t)n * 512 + k0 + cc * 8);
            }
        }
        CP_COMMIT();
    };

    issue(0, 0);

    for (int j = 0; j < T; ++j) {
        const int s = j & 1;
        __nv_bfloat16* Ah = (__nv_bfloat16*)(smem + OFF_AS + (s * 2 + 0) * PLANE_B);
        __nv_bfloat16* Al = (__nv_bfloat16*)(smem + OFF_AS + (s * 2 + 1) * PLANE_B);
        const __nv_bfloat16* Bh = (const __nv_bfloat16*)(smem + OFF_BS + (s * 2 + 0) * PLANE_B);
        const __nv_bfloat16* Bl = (const __nv_bfloat16*)(smem + OFF_BS + (s * 2 + 1) * PLANE_B);

        // ---- A(j) staged: convert fp32 -> bf16 hi/lo tiles ----
        CP_WAIT1();            // completes A group of chunk j
        __syncthreads();
        {
            const float* ar = Afp + tid * APITCH;     // row `tid`, 32 floats
            uint32_t hp[16], lp[16];
            #pragma unroll
            for (int cc = 0; cc < 8; ++cc) {
                float4 f = *(const float4*)(ar + cc * 4);
                __nv_bfloat16 h0 = __float2bfloat16_rn(f.x);
                __nv_bfloat16 h1 = __float2bfloat16_rn(f.y);
                __nv_bfloat16 h2 = __float2bfloat16_rn(f.z);
                __nv_bfloat16 h3 = __float2bfloat16_rn(f.w);
                float l0 = f.x - __bfloat162float(h0);
                float l1 = f.y - __bfloat162float(h1);
                float l2 = f.z - __bfloat162float(h2);
                float l3 = f.w - __bfloat162float(h3);
                __nv_bfloat162 ph0 = __halves2bfloat162(h0, h1);
                __nv_bfloat162 ph1 = __halves2bfloat162(h2, h3);
                __nv_bfloat162 pl0 = __halves2bfloat162(__float2bfloat16_rn(l0), __float2bfloat16_rn(l1));
                __nv_bfloat162 pl1 = __halves2bfloat162(__float2bfloat16_rn(l2), __float2bfloat16_rn(l3));
                hp[cc * 2 + 0] = *(uint32_t*)&ph0;
                hp[cc * 2 + 1] = *(uint32_t*)&ph1;
                lp[cc * 2 + 0] = *(uint32_t*)&pl0;
                lp[cc * 2 + 1] = *(uint32_t*)&pl1;
            }
            uint32_t* dh = (uint32_t*)(Ah + tid * SP);
            uint32_t* dl = (uint32_t*)(Al + tid * SP);
            #pragma unroll
            for (int cc = 0; cc < 4; ++cc) {
                *(uint4*)(dh + cc * 4) = *(uint4*)(hp + cc * 4);
                *(uint4*)(dl + cc * 4) = *(uint4*)(lp + cc * 4);
            }
        }
        CP_WAIT0();            // completes B group of chunk j
        __syncthreads();       // tiles ready; Afp fully consumed

        if (j + 1 < T) issue(j + 1, s ^ 1);

        // ---- MMA: 3 terms (AhBh, AhBl, AlBh), 2 k16 halves each ----
        #pragma unroll
        for (int term = 0; term < 3; ++term) {
            const __nv_bfloat16* Ap = (term == 2) ? Al : Ah;
            const __nv_bfloat16* Bp = (term == 1) ? Bl : Bh;
            #pragma unroll
            for (int h = 0; h < 2; ++h) {
                const int kb = h * 16 + (lane & 3) * 2;
                uint32_t a[4][4], b[8][2];
                #pragma unroll
                for (int i = 0; i < 4; ++i) {
                    const __nv_bfloat16* p =
                        Ap + (warp_m * 64 + i * 16 + (lane >> 2)) * SP + kb;
                    a[i][0] = *(const uint32_t*)p;
                    a[i][1] = *(const uint32_t*)(p + 8 * SP);
                    a[i][2] = *(const uint32_t*)(p + 8);
                    a[i][3] = *(const uint32_t*)(p + 8 * SP + 8);
                }
                #pragma unroll
                for (int jj = 0; jj < 8; ++jj) {
                    const __nv_bfloat16* p =
                        Bp + (warp_n * 64 + jj * 8 + (lane >> 2)) * SP + kb;
                    b[jj][0] = *(const uint32_t*)p;
                    b[jj][1] = *(const uint32_t*)(p + 8);
                }
                #pragma unroll
                for (int i = 0; i < 4; ++i)
                    #pragma unroll
                    for (int jj = 0; jj < 8; ++jj)
                        mma16816(c[i][jj], a[i], b[jj]);
            }
        }
    }

    // ---- epilogue: bias + relu + store ----
    #pragma unroll
    for (int i = 0; i < 4; ++i) {
        int r0 = m0 + warp_m * 64 + i * 16 + (lane >> 2);
        #pragma unroll
        for (int jj = 0; jj < 8; ++jj) {
            int col = warp_n * 64 + jj * 8 + (lane & 3) * 2;
            float b0 = __ldg(&bias[col]), b1 = __ldg(&bias[col + 1]);
            float2 v0 = make_float2(c[i][jj][0] + b0, c[i][jj][1] + b1);
            float2 v1 = make_float2(c[i][jj][2] + b0, c[i][jj][3] + b1);
            if (relu) {
                v0.x = fmaxf(v0.x, 0.f); v0.y = fmaxf(v0.y, 0.f);
                v1.x = fmaxf(v1.x, 0.f); v1.y = fmaxf(v1.y, 0.f);
            }
            if (r0 < Mtot)     *(float2*)(C + (size_t)r0 * 128 + col)       = v0;
            if (r0 + 8 < Mtot) *(float2*)(C + (size_t)(r0 + 8) * 128 + col) = v1;
        }
    }
}

// ---------------- classifier tail: out[NT,16] = h3 @ Wc2 + bc2 ----------------
__global__ void __launch_bounds__(256) k_cls(const float* __restrict__ Wc2,
                                             const float* __restrict__ bc2,
                                             float* __restrict__ outp)
{
    __shared__ float w[HID * NCLS];
    __shared__ float bb[NCLS];
    int tid = threadIdx.x;
    for (int i = tid; i < HID * NCLS; i += 256) w[i] = Wc2[i];
    if (tid < NCLS) bb[tid] = bc2[tid];
    __syncthreads();

    int row = blockIdx.x * 16 + (tid >> 4);
    int col = tid & 15;
    if (row >= NT) return;
    const float* hr = g_h3 + (size_t)row * HID;
    float acc = bb[col];
    #pragma unroll 8
    for (int k = 0; k < HID; ++k)
        acc += hr[k] * w[k * NCLS + col];
    outp[(size_t)row * NCLS + col] = acc;
}

// ---------------- launch ----------------
extern "C" void kernel_launch(void* const* d_in, const int* in_sizes, int n_in,
                              void* d_out, int out_size)
{
    const float* gene  = (const float*)d_in[0];
    const float* train = (const float*)d_in[1];
    const int*   esrc  = (const int*)  d_in[2];
    const int*   edst  = (const int*)  d_in[3];
    const float* W1n   = (const float*)d_in[4];
    const float* W1s   = (const float*)d_in[5];
    const float* b1    = (const float*)d_in[6];
    const float* W2n   = (const float*)d_in[7];
    const float* W2s   = (const float*)d_in[8];
    const float* b2    = (const float*)d_in[9];
    const float* Wc1   = (const float*)d_in[10];
    const float* bc1   = (const float*)d_in[11];
    const float* Wc2   = (const float*)d_in[12];
    const float* bc2   = (const float*)d_in[13];
    float* out = (float*)d_out;

    float *agg, *h1, *h2, *h3;
    __nv_bfloat16* wtb;
    cudaGetSymbolAddress((void**)&agg, g_agg);
    cudaGetSymbolAddress((void**)&h1,  g_h1);
    cudaGetSymbolAddress((void**)&h2,  g_h2);
    cudaGetSymbolAddress((void**)&h3,  g_h3);
    cudaGetSymbolAddress((void**)&wtb, g_wtb);

    static bool attr_done = false;
    if (!attr_done) {
        cudaFuncSetAttribute(gemm_mma, cudaFuncAttributeMaxDynamicSharedMemorySize, SMEM_GEMM);
        attr_done = true;
    }

    k_tr<<<(5 * 128 * 512 + 255) / 256, 256>>>(W1s, W1n, W2s, W2n, Wc1);
    k_init<<<(NT + 255) / 256, 256>>>();
    k_hist<<<(NE + 255) / 256, 256>>>(edst);
    k_scan<<<1, 1024>>>();
    k_scatter<<<(NE + 255) / 256, 256>>>(esrc, edst);
    k_spmm<<<(NT * 32 + 255) / 256, 256>>>(gene);

    const int grid = (NT + 127) / 128;  // 157
    const size_t WSTRIDE = (size_t)2 * 128 * 512;
    // h1 = relu(train @ W1s + agg @ W1n + b1)
    gemm_mma<<<grid, 128, SMEM_GEMM>>>(train, DST_DIM, 16, wtb + 0 * WSTRIDE,
                                       agg, 4, wtb + 1 * WSTRIDE, b1, h1, NT, 1);
    // h2 = relu(h1 @ W2s + agg @ W2n + b2)
    gemm_mma<<<grid, 128, SMEM_GEMM>>>(h1, HID, 4, wtb + 2 * WSTRIDE,
                                       agg, 4, wtb + 3 * WSTRIDE, b2, h2, NT, 1);
    // h3 = relu(h2 @ Wc1 + bc1)
    gemm_mma<<<grid, 128, SMEM_GEMM>>>(h2, OUTD, 4, wtb + 4 * WSTRIDE,
                                       (const float*)nullptr, 0, (const __nv_bfloat16*)nullptr,
                                       bc1, h3, NT, 1);
    k_cls<<<(NT + 15) / 16, 256>>>(Wc2, bc2, out);

    (void)in_sizes; (void)n_in; (void)out_size;
}

// round 6
// speedup vs baseline: 2.8180x; 1.0348x over previous
#include <cuda_runtime.h>
#include <cuda_bf16.h>
#include <cstdint>

static constexpr int NG      = 2500;
static constexpr int NT      = 20000;
static constexpr int NE      = 640000;
static constexpr int SRC_DIM = 128;
static constexpr int DST_DIM = 500;
static constexpr int HID     = 128;
static constexpr int OUTD    = 128;
static constexpr int NCLS    = 16;

// ---------------- scratch (device globals: no allocation allowed) ----------------
__device__ float g_agg[NT * SRC_DIM];
__device__ float g_h1[NT * HID];
__device__ float g_h2[NT * OUTD];
__device__ float g_h3[NT * OUTD];
__device__ int   g_deg[NT];
__device__ int   g_rowptr[NT + 1];
__device__ int   g_cursor[NT];
__device__ int   g_colidx[NE];
// weights as bf16 hi/lo planes: [w][plane][n(128)][k(512 padded)]
__device__ __nv_bfloat16 g_wtb[5 * 2 * 128 * 512];

// ---------------- weight transpose + bf16 split (also zeros g_deg) ----------------
__global__ void k_tr(const float* __restrict__ W1s, const float* __restrict__ W1n,
                     const float* __restrict__ W2s, const float* __restrict__ W2n,
                     const float* __restrict__ Wc1) {
    int idx = blockIdx.x * blockDim.x + threadIdx.x;
    if (idx < NT) g_deg[idx] = 0;          // folded k_init
    if (idx >= 5 * 128 * 512) return;
    int w   = idx >> 16;
    int rem = idx & 65535;
    int n   = rem >> 9;
    int k   = rem & 511;
    const float* W = (w == 0) ? W1s : (w == 1) ? W1n : (w == 2) ? W2s : (w == 3) ? W2n : Wc1;
    int K = (w == 0) ? DST_DIM : 128;
    float v = (k < K) ? W[(size_t)k * 128 + n] : 0.f;
    __nv_bfloat16 hb = __float2bfloat16_rn(v);
    float lo = v - __bfloat162float(hb);
    g_wtb[(size_t)w * 2 * 128 * 512 + (size_t)n * 512 + k] = hb;
    g_wtb[(size_t)w * 2 * 128 * 512 + 128 * 512 + (size_t)n * 512 + k] = __float2bfloat16_rn(lo);
}

// ---------------- CSR build ----------------
__global__ void k_hist(const int* __restrict__ dst) {
    int e0 = (blockIdx.x * blockDim.x + threadIdx.x) * 2;
    #pragma unroll
    for (int q = 0; q < 2; ++q) {
        int e = e0 + q;
        if (e < NE) atomicAdd(&g_deg[__ldg(&dst[e])], 1);
    }
}

// single-pass hierarchical scan: 1024 threads x 20 sequential elements
__global__ void __launch_bounds__(1024) k_scan() {
    constexpr int PER = 20;                 // 1024*20 = 20480 >= NT
    __shared__ int wsum[32];
    const int tid  = threadIdx.x;
    const int lane = tid & 31;
    const int wid  = tid >> 5;
    const int base = tid * PER;

    int pref[PER];
    int s = 0;
    #pragma unroll
    for (int q = 0; q < PER; ++q) {
        int i = base + q;
        int d = (i < NT) ? g_deg[i] : 0;
        pref[q] = s;
        s += d;
    }
    // warp inclusive scan of per-thread sums
    int x = s;
    #pragma unroll
    for (int off = 1; off < 32; off <<= 1) {
        int y = __shfl_up_sync(0xffffffffu, x, off);
        if (lane >= off) x += y;
    }
    if (lane == 31) wsum[wid] = x;
    __syncthreads();
    if (wid == 0) {
        int w = wsum[lane];
        #pragma unroll
        for (int off = 1; off < 32; off <<= 1) {
            int y = __shfl_up_sync(0xffffffffu, w, off);
            if (lane >= off) w += y;
        }
        wsum[lane] = w;
    }
    __syncthreads();
    const int tbase = (x - s) + (wid ? wsum[wid - 1] : 0);
    #pragma unroll
    for (int q = 0; q < PER; ++q) {
        int i = base + q;
        if (i < NT) {
            int rp = tbase + pref[q];
            g_rowptr[i] = rp;
            g_cursor[i] = rp;
        }
    }
    if (tid == 1023) g_rowptr[NT] = tbase + s;   // base>=NT here, so tbase+s = total
}

__global__ void k_scatter(const int* __restrict__ src, const int* __restrict__ dst) {
    int e0 = (blockIdx.x * blockDim.x + threadIdx.x) * 2;
    #pragma unroll
    for (int q = 0; q < 2; ++q) {
        int e = e0 + q;
        if (e < NE) {
            int p = atomicAdd(&g_cursor[__ldg(&dst[e])], 1);
            g_colidx[p] = __ldg(&src[e]);
        }
    }
}

// ---------------- SpMM mean: one warp per dst row ----------------
__global__ void __launch_bounds__(256) k_spmm(const float* __restrict__ gene) {
    int row  = (blockIdx.x * blockDim.x + threadIdx.x) >> 5;
    int lane = threadIdx.x & 31;
    if (row >= NT) return;
    int beg = g_rowptr[row];
    int end = g_rowptr[row + 1];
    float4 a = make_float4(0.f, 0.f, 0.f, 0.f);
    for (int base = beg; base < end; base += 32) {
        int myidx = (base + lane < end) ? g_colidx[base + lane] : 0;
        int cnt = min(32, end - base);
        int j = 0;
        for (; j + 4 <= cnt; j += 4) {
            int s0 = __shfl_sync(0xffffffffu, myidx, j);
            int s1 = __shfl_sync(0xffffffffu, myidx, j + 1);
            int s2 = __shfl_sync(0xffffffffu, myidx, j + 2);
            int s3 = __shfl_sync(0xffffffffu, myidx, j + 3);
            float4 v0 = *((const float4*)(gene + (size_t)s0 * SRC_DIM) + lane);
            float4 v1 = *((const float4*)(gene + (size_t)s1 * SRC_DIM) + lane);
            float4 v2 = *((const float4*)(gene + (size_t)s2 * SRC_DIM) + lane);
            float4 v3 = *((const float4*)(gene + (size_t)s3 * SRC_DIM) + lane);
            a.x += v0.x + v1.x + v2.x + v3.x;
            a.y += v0.y + v1.y + v2.y + v3.y;
            a.z += v0.z + v1.z + v2.z + v3.z;
            a.w += v0.w + v1.w + v2.w + v3.w;
        }
        for (; j < cnt; ++j) {
            int s = __shfl_sync(0xffffffffu, myidx, j);
            float4 v = *((const float4*)(gene + (size_t)s * SRC_DIM) + lane);
            a.x += v.x; a.y += v.y; a.z += v.z; a.w += v.w;
        }
    }
    float inv = 1.0f / (float)max(end - beg, 1);
    a.x *= inv; a.y *= inv; a.z *= inv; a.w *= inv;
    *((float4*)(g_agg + (size_t)row * SRC_DIM) + lane) = a;
}

// ---------------- mma.sync bf16 GEMM (3-term split), dual-source fused ----------------
static constexpr int SP      = 40;                 // bf16 smem pitch (80B, conflict-free)
static constexpr int APITCH  = 36;                 // fp32 staging pitch (144B)
static constexpr int PLANE_B = 128 * SP * 2;       // 10240 bytes per plane-stage tile
static constexpr int OFF_AS  = 0;                  // 4 tiles: [stage][plane]
static constexpr int OFF_BS  = 4 * PLANE_B;        // 40960
static constexpr int OFF_AFP = 8 * PLANE_B;        // 81920
static constexpr int SMEM_GEMM = OFF_AFP + 128 * APITCH * 4;   // 100352

__device__ __forceinline__ uint32_t smem_u32(const void* p) {
    uint32_t a;
    asm("{ .reg .u64 t; cvta.to.shared.u64 t, %1; cvt.u32.u64 %0, t; }" : "=r"(a) : "l"(p));
    return a;
}
#define CP16(dst, src) \
    asm volatile("cp.async.ca.shared.global [%0], [%1], 16;" :: "r"(dst), "l"(src))
#define CP16Z(dst, src, nb) \
    asm volatile("cp.async.ca.shared.global [%0], [%1], 16, %2;" :: "r"(dst), "l"(src), "r"(nb))
#define CP_COMMIT() asm volatile("cp.async.commit_group;" ::: "memory")
#define CP_WAIT1()  asm volatile("cp.async.wait_group 1;" ::: "memory")
#define CP_WAIT0()  asm volatile("cp.async.wait_group 0;" ::: "memory")

__device__ __forceinline__ void mma16816(float* c, const uint32_t* a, const uint32_t* b) {
    asm volatile(
        "mma.sync.aligned.m16n8k16.row.col.f32.bf16.bf16.f32 "
        "{%0,%1,%2,%3}, {%4,%5,%6,%7}, {%8,%9}, {%0,%1,%2,%3};"
        : "+f"(c[0]), "+f"(c[1]), "+f"(c[2]), "+f"(c[3])
        : "r"(a[0]), "r"(a[1]), "r"(a[2]), "r"(a[3]), "r"(b[0]), "r"(b[1]));
}

__global__ void __launch_bounds__(128, 2) gemm_mma(
    const float* __restrict__ A1, int K1, int nch1, const __nv_bfloat16* __restrict__ B1,
    const float* __restrict__ A2, int nch2, const __nv_bfloat16* __restrict__ B2,
    const float* __restrict__ bias, float* __restrict__ C, int Mtot, int relu)
{
    extern __shared__ __align__(16) char smem[];
    const int tid    = threadIdx.x;
    const int lane   = tid & 31;
    const int wid    = tid >> 5;
    const int warp_m = wid >> 1;
    const int warp_n = wid & 1;
    const int m0     = blockIdx.x * 128;
    const int T      = nch1 + nch2;

    const uint32_t afp_u = smem_u32(smem + OFF_AFP);
    const uint32_t bs_u  = smem_u32(smem + OFF_BS);
    float* Afp = (float*)(smem + OFF_AFP);

    float c[4][8][4];
    #pragma unroll
    for (int i = 0; i < 4; ++i)
        #pragma unroll
        for (int j = 0; j < 8; ++j)
            #pragma unroll
            for (int q = 0; q < 4; ++q) c[i][j][q] = 0.f;

    auto issue = [&](int cj, int stage) {
        const float* A; const __nv_bfloat16* Bw; int K, k0;
        if (cj < nch1) { A = A1; Bw = B1; K = K1; k0 = cj << 5; }
        else           { A = A2; Bw = B2; K = 128; k0 = (cj - nch1) << 5; }
        #pragma unroll
        for (int i = 0; i < 8; ++i) {
            int idx = i * 128 + tid;
            int row = idx >> 3, cc = idx & 7;
            int gr = m0 + row, k = k0 + cc * 4;
            int nb = 0;
            if (gr < Mtot) { int rem = K - k; nb = (rem >= 4) ? 16 : (rem > 0 ? rem * 4 : 0); }
            const float* src = nb ? (A + (size_t)gr * K + k) : A;
            CP16Z(afp_u + row * 144 + cc * 16, src, nb);
        }
        CP_COMMIT();
        #pragma unroll
        for (int p = 0; p < 2; ++p) {
            const __nv_bfloat16* bp = Bw + (size_t)p * 128 * 512;
            uint32_t bd = bs_u + (stage * 2 + p) * PLANE_B;
            #pragma unroll
            for (int i = 0; i < 4; ++i) {
                int idx = i * 128 + tid;
                int n = idx >> 2, cc = idx & 3;
                CP16(bd + n * 80 + cc * 16, bp + (size_t)n * 512 + k0 + cc * 8);
            }
        }
        CP_COMMIT();
    };

    issue(0, 0);

    for (int j = 0; j < T; ++j) {
        const int s = j & 1;
        __nv_bfloat16* Ah = (__nv_bfloat16*)(smem + OFF_AS + (s * 2 + 0) * PLANE_B);
        __nv_bfloat16* Al = (__nv_bfloat16*)(smem + OFF_AS + (s * 2 + 1) * PLANE_B);
        const __nv_bfloat16* Bh = (const __nv_bfloat16*)(smem + OFF_BS + (s * 2 + 0) * PLANE_B);
        const __nv_bfloat16* Bl = (const __nv_bfloat16*)(smem + OFF_BS + (s * 2 + 1) * PLANE_B);

        CP_WAIT1();
        __syncthreads();
        {
            const float* ar = Afp + tid * APITCH;
            uint32_t hp[16], lp[16];
            #pragma unroll
            for (int cc = 0; cc < 8; ++cc) {
                float4 f = *(const float4*)(ar + cc * 4);
                __nv_bfloat16 h0 = __float2bfloat16_rn(f.x);
                __nv_bfloat16 h1 = __float2bfloat16_rn(f.y);
                __nv_bfloat16 h2 = __float2bfloat16_rn(f.z);
                __nv_bfloat16 h3 = __float2bfloat16_rn(f.w);
                float l0 = f.x - __bfloat162float(h0);
                float l1 = f.y - __bfloat162float(h1);
                float l2 = f.z - __bfloat162float(h2);
                float l3 = f.w - __bfloat162float(h3);
                __nv_bfloat162 ph0 = __halves2bfloat162(h0, h1);
                __nv_bfloat162 ph1 = __halves2bfloat162(h2, h3);
                __nv_bfloat162 pl0 = __halves2bfloat162(__float2bfloat16_rn(l0), __float2bfloat16_rn(l1));
                __nv_bfloat162 pl1 = __halves2bfloat162(__float2bfloat16_rn(l2), __float2bfloat16_rn(l3));
                hp[cc * 2 + 0] = *(uint32_t*)&ph0;
                hp[cc * 2 + 1] = *(uint32_t*)&ph1;
                lp[cc * 2 + 0] = *(uint32_t*)&pl0;
                lp[cc * 2 + 1] = *(uint32_t*)&pl1;
            }
            uint32_t* dh = (uint32_t*)(Ah + tid * SP);
            uint32_t* dl = (uint32_t*)(Al + tid * SP);
            #pragma unroll
            for (int cc = 0; cc < 4; ++cc) {
                *(uint4*)(dh + cc * 4) = *(uint4*)(hp + cc * 4);
                *(uint4*)(dl + cc * 4) = *(uint4*)(lp + cc * 4);
            }
        }
        CP_WAIT0();
        __syncthreads();

        if (j + 1 < T) issue(j + 1, s ^ 1);

        #pragma unroll
        for (int term = 0; term < 3; ++term) {
            const __nv_bfloat16* Ap = (term == 2) ? Al : Ah;
            const __nv_bfloat16* Bp = (term == 1) ? Bl : Bh;
            #pragma unroll
            for (int h = 0; h < 2; ++h) {
                const int kb = h * 16 + (lane & 3) * 2;
                uint32_t a[4][4], b[8][2];
                #pragma unroll
                for (int i = 0; i < 4; ++i) {
                    const __nv_bfloat16* p =
                        Ap + (warp_m * 64 + i * 16 + (lane >> 2)) * SP + kb;
                    a[i][0] = *(const uint32_t*)p;
                    a[i][1] = *(const uint32_t*)(p + 8 * SP);
                    a[i][2] = *(const uint32_t*)(p + 8);
                    a[i][3] = *(const uint32_t*)(p + 8 * SP + 8);
                }
                #pragma unroll
                for (int jj = 0; jj < 8; ++jj) {
                    const __nv_bfloat16* p =
                        Bp + (warp_n * 64 + jj * 8 + (lane >> 2)) * SP + kb;
                    b[jj][0] = *(const uint32_t*)p;
                    b[jj][1] = *(const uint32_t*)(p + 8);
                }
                #pragma unroll
                for (int i = 0; i < 4; ++i)
                    #pragma unroll
                    for (int jj = 0; jj < 8; ++jj)
                        mma16816(c[i][jj], a[i], b[jj]);
            }
        }
    }

    #pragma unroll
    for (int i = 0; i < 4; ++i) {
        int r0 = m0 + warp_m * 64 + i * 16 + (lane >> 2);
        #pragma unroll
        for (int jj = 0; jj < 8; ++jj) {
            int col = warp_n * 64 + jj * 8 + (lane & 3) * 2;
            float b0 = __ldg(&bias[col]), b1 = __ldg(&bias[col + 1]);
            float2 v0 = make_float2(c[i][jj][0] + b0, c[i][jj][1] + b1);
            float2 v1 = make_float2(c[i][jj][2] + b0, c[i][jj][3] + b1);
            if (relu) {
                v0.x = fmaxf(v0.x, 0.f); v0.y = fmaxf(v0.y, 0.f);
                v1.x = fmaxf(v1.x, 0.f); v1.y = fmaxf(v1.y, 0.f);
            }
            if (r0 < Mtot)     *(float2*)(C + (size_t)r0 * 128 + col)       = v0;
            if (r0 + 8 < Mtot) *(float2*)(C + (size_t)(r0 + 8) * 128 + col) = v1;
        }
    }
}

// ---------------- classifier tail: out[NT,16] = h3 @ Wc2 + bc2 ----------------
__global__ void __launch_bounds__(256) k_cls(const float* __restrict__ Wc2,
                                             const float* __restrict__ bc2,
                                             float* __restrict__ outp)
{
    __shared__ float w[HID * NCLS];
    __shared__ float bb[NCLS];
    int tid = threadIdx.x;
    for (int i = tid; i < HID * NCLS; i += 256) w[i] = Wc2[i];
    if (tid < NCLS) bb[tid] = bc2[tid];
    __syncthreads();

    int row = blockIdx.x * 16 + (tid >> 4);
    int col = tid & 15;
    if (row >= NT) return;
    const float* hr = g_h3 + (size_t)row * HID;
    float acc = bb[col];
    #pragma unroll 8
    for (int k = 0; k < HID; ++k)
        acc += hr[k] * w[k * NCLS + col];
    outp[(size_t)row * NCLS + col] = acc;
}

// ---------------- launch ----------------
extern "C" void kernel_launch(void* const* d_in, const int* in_sizes, int n_in,
                              void* d_out, int out_size)
{
    const float* gene  = (const float*)d_in[0];
    const float* train = (const float*)d_in[1];
    const int*   esrc  = (const int*)  d_in[2];
    const int*   edst  = (const int*)  d_in[3];
    const float* W1n   = (const float*)d_in[4];
    const float* W1s   = (const float*)d_in[5];
    const float* b1    = (const float*)d_in[6];
    const float* W2n   = (const float*)d_in[7];
    const float* W2s   = (const float*)d_in[8];
    const float* b2    = (const float*)d_in[9];
    const float* Wc1   = (const float*)d_in[10];
    const float* bc1   = (const float*)d_in[11];
    const float* Wc2   = (const float*)d_in[12];
    const float* bc2   = (const float*)d_in[13];
    float* out = (float*)d_out;

    float *agg, *h1, *h2, *h3;
    __nv_bfloat16* wtb;
    cudaGetSymbolAddress((void**)&agg, g_agg);
    cudaGetSymbolAddress((void**)&h1,  g_h1);
    cudaGetSymbolAddress((void**)&h2,  g_h2);
    cudaGetSymbolAddress((void**)&h3,  g_h3);
    cudaGetSymbolAddress((void**)&wtb, g_wtb);

    static bool attr_done = false;
    if (!attr_done) {
        cudaFuncSetAttribute(gemm_mma, cudaFuncAttributeMaxDynamicSharedMemorySize, SMEM_GEMM);
        attr_done = true;
    }

    k_tr<<<(5 * 128 * 512 + 255) / 256, 256>>>(W1s, W1n, W2s, W2n, Wc1);
    k_hist<<<(NE / 2 + 255) / 256, 256>>>(edst);
    k_scan<<<1, 1024>>>();
    k_scatter<<<(NE / 2 + 255) / 256, 256>>>(esrc, edst);
    k_spmm<<<(NT * 32 + 255) / 256, 256>>>(gene);

    const int grid = (NT + 127) / 128;  // 157
    const size_t WSTRIDE = (size_t)2 * 128 * 512;
    gemm_mma<<<grid, 128, SMEM_GEMM>>>(train, DST_DIM, 16, wtb + 0 * WSTRIDE,
                                       agg, 4, wtb + 1 * WSTRIDE, b1, h1, NT, 1);
    gemm_mma<<<grid, 128, SMEM_GEMM>>>(h1, HID, 4, wtb + 2 * WSTRIDE,
                                       agg, 4, wtb + 3 * WSTRIDE, b2, h2, NT, 1);
    gemm_mma<<<grid, 128, SMEM_GEMM>>>(h2, OUTD, 4, wtb + 4 * WSTRIDE,
                                       (const float*)nullptr, 0, (const __nv_bfloat16*)nullptr,
                                       bc1, h3, NT, 1);
    k_cls<<<(NT + 15) / 16, 256>>>(Wc2, bc2, out);

    (void)in_sizes; (void)n_in; (void)out_size;
}